// round 5
// baseline (speedup 1.0000x reference)
#include <cuda_runtime.h>

#define HW 16384
#define OFF_PI 0
#define OFF_MU 2097152
#define OFF_SIG 35651584
#define OFF_G 37748736

// shared layout (float offsets)
#define SH_A 0         // 152*128 : A tile [c][pix]  (x | mu | rho)
#define SH_B 19456     // 152*128 : Wmu^T [c][o]
#define SH_S 38912     // 152*8   : Wsig^T [c][j]
#define SH_BMU 40128   // 128
#define SH_WPI 40256   // 128
#define SH_MISC 40384  // 32 : bpi[0..7] bsig[8..15] Wg[16..23] bg[24]
#define SH_AL 40416    // 8*128
#define SH_PIV 41440   // 8*128
#define SH_PIN 42464   // 8*128
#define SH_SIG 43488   // 8*128 : sigma-matvec mu_new partials
#define SH_D2 44512    // 8*128 : dist2 partials
#define SH_TOT 45536
#define SMEM_BYTES (SH_TOT * 4)

typedef unsigned long long ull;

__device__ __forceinline__ ull pack2(float a, float b) {
    ull r;
    asm("mov.b64 %0, {%1,%2};" : "=l"(r) : "f"(a), "f"(b));
    return r;
}
__device__ __forceinline__ ull ffma2(ull a, ull b, ull c) {
    ull d;
    asm("fma.rn.f32x2 %0, %1, %2, %3;" : "=l"(d) : "l"(a), "l"(b), "l"(c));
    return d;
}
__device__ __forceinline__ float2 unpack2(ull v) {
    float2 f;
    asm("mov.b64 {%0,%1}, %2;" : "=f"(f.x), "=f"(f.y) : "l"(v));
    return f;
}

extern "C" __global__ void __launch_bounds__(512, 1)
gmm_block_kernel(const float* __restrict__ x, const float* __restrict__ pi_in,
                 const float* __restrict__ mu, const float* __restrict__ sigma,
                 const float* __restrict__ Wpi, const float* __restrict__ bpi,
                 const float* __restrict__ Wmu, const float* __restrict__ bmu,
                 const float* __restrict__ Wsig, const float* __restrict__ bsig,
                 const float* __restrict__ Wg, const float* __restrict__ bg,
                 float* __restrict__ out) {
    extern __shared__ float sh[];
    const int tid = threadIdx.x;
    const int blk = blockIdx.x;          // 2048 CTAs, 128 pixels each
    const int b = blk >> 7;
    const int hw0 = (blk & 127) << 7;

    // ---------------- stage 1: stage weights + x tile, zero reductions -----
    for (int i = tid; i < 2048; i += 512) {
        int c = i >> 7, p = i & 127;
        sh[SH_A + c * 128 + p] = x[(b * 16 + c) * HW + hw0 + p];
    }
    for (int i = tid; i < 19456; i += 512) {   // Wmu[o][c] -> shB[c][o]
        int o = i / 152, c = i - o * 152;
        sh[SH_B + c * 128 + o] = Wmu[i];
    }
    for (int i = tid; i < 1216; i += 512) {    // Wsig[j][c] -> shS[c][j]
        int j = i / 152, c = i - j * 152;
        sh[SH_S + c * 8 + j] = Wsig[i];
    }
    if (tid < 128) {
        sh[SH_BMU + tid] = bmu[tid];
        sh[SH_WPI + tid] = Wpi[tid];
    } else if (tid < 136) {
        int k = tid - 128;
        sh[SH_MISC + k] = bpi[k];
        sh[SH_MISC + 8 + k] = bsig[k];
        sh[SH_MISC + 16 + k] = Wg[k];
    }
    if (tid == 511) sh[SH_MISC + 24] = bg[0];
    for (int i = tid; i < 1024; i += 512) {
        sh[SH_SIG + i] = 0.f;
        sh[SH_D2 + i] = 0.f;
    }
    __syncthreads();

    // ---------------- stage 2: stream mu once, fuse dens/alpha/rho ---------
    {
        const int p = tid & 127, grp = tid >> 7;  // 4 groups x 2 components
        const float* mup = mu + (b * 128) * HW + hw0 + p;
#pragma unroll
        for (int kg = 0; kg < 2; kg++) {
            int k = grp * 2 + kg;
            float dk = 0.f;
#pragma unroll
            for (int c = 0; c < 16; c++) {
                int ch = k * 16 + c;
                float v = mup[ch * HW];
                sh[SH_A + (16 + ch) * 128 + p] = v;
                float d = sh[SH_A + c * 128 + p] - v;
                dk = fmaf(d, d, dk);
            }
            float sg = sigma[(b * 8 + k) * HW + hw0 + p];
            float pv = pi_in[(b * 8 + k) * HW + hw0 + p];
            float s2 = sg * sg;
            float t = 6.283185307179586f * s2;
            float t2 = t * t, t4 = t2 * t2;
            float dens = __expf(-dk / (2.f * s2)) / (t4 * t4);
            float a = pv * dens;
            sh[SH_AL + k * 128 + p] = a;
            sh[SH_PIV + k * 128 + p] = pv;
            sh[SH_A + (144 + k) * 128 + p] = a * dens;  // rho
        }
    }
    __syncthreads();

    // ---------------- stage 3: pi_new (softmax), 128 threads ---------------
    if (tid < 128) {
        const int p = tid;
        float piv[8], al[8], z[8];
#pragma unroll
        for (int k = 0; k < 8; k++) {
            piv[k] = sh[SH_PIV + k * 128 + p];
            al[k] = sh[SH_AL + k * 128 + p];
        }
        float zmax = -1e30f;
#pragma unroll
        for (int j = 0; j < 8; j++) {
            float zj = sh[SH_MISC + j];
#pragma unroll
            for (int i = 0; i < 8; i++) {
                zj = fmaf(sh[SH_WPI + j * 16 + i], piv[i], zj);
                zj = fmaf(sh[SH_WPI + j * 16 + 8 + i], al[i], zj);
            }
            z[j] = zj;
            zmax = fmaxf(zmax, zj);
        }
        float s = 0.f;
#pragma unroll
        for (int j = 0; j < 8; j++) {
            z[j] = __expf(z[j] - zmax);
            s += z[j];
        }
        float inv = 1.0f / s;
#pragma unroll
        for (int j = 0; j < 8; j++) {
            float pn = z[j] * inv;
            sh[SH_PIN + j * 128 + p] = pn;
            out[OFF_PI + (b * 8 + j) * HW + hw0 + p] = pn;
        }
    }

    // ---------------- stage 4: tiled GEMM, 8x4 microtile per thread --------
    const int tm = tid & 15;   // pixel octet   (8 pixels)
    const int tn = tid >> 4;   // output quartet (4 outputs), 0..31
    const float* Abase = sh + SH_A + tm * 8;
    const float* Bbase = sh + SH_B + tn * 4;

    ull acc[16];
    {
        float4 m0 = *(const float4*)(sh + SH_BMU + tn * 4);
        float bb[4] = {m0.x, m0.y, m0.z, m0.w};
#pragma unroll
        for (int o = 0; o < 4; o++)
#pragma unroll
            for (int pp = 0; pp < 4; pp++) acc[o * 4 + pp] = pack2(bb[o], bb[o]);
    }

#pragma unroll 1
    for (int c0 = 0; c0 < 152; c0 += 8) {
#pragma unroll
        for (int u = 0; u < 8; u++) {
            const int c = c0 + u;
            const float* ap = Abase + c * 128;
            ulonglong2 a01 = *(const ulonglong2*)ap;
            ulonglong2 a23 = *(const ulonglong2*)(ap + 4);
            float4 bv = *(const float4*)(Bbase + c * 128);
            ull ad[4] = {a01.x, a01.y, a23.x, a23.y};
            float bs[4] = {bv.x, bv.y, bv.z, bv.w};
#pragma unroll
            for (int o = 0; o < 4; o++) {
                ull bbp = pack2(bs[o], bs[o]);
#pragma unroll
                for (int pp = 0; pp < 4; pp++)
                    acc[o * 4 + pp] = ffma2(ad[pp], bbp, acc[o * 4 + pp]);
            }
        }
    }

    // ---------------- stage 5: relu + store mu_new + partial reductions ----
#pragma unroll
    for (int i = 0; i < 16; i++) {
        float2 f = unpack2(acc[i]);
        acc[i] = pack2(fmaxf(f.x, 0.f), fmaxf(f.y, 0.f));
    }
    {
        float* outMu = out + OFF_MU + (b * 128 + tn * 4) * HW + hw0 + tm * 8;
#pragma unroll
        for (int o = 0; o < 4; o++) {
            float2 q0 = unpack2(acc[o * 4 + 0]);
            float2 q1 = unpack2(acc[o * 4 + 1]);
            float2 q2 = unpack2(acc[o * 4 + 2]);
            float2 q3 = unpack2(acc[o * 4 + 3]);
            *(float4*)(outMu + o * HW) = make_float4(q0.x, q0.y, q1.x, q1.y);
            *(float4*)(outMu + o * HW + 4) = make_float4(q2.x, q2.y, q3.x, q3.y);
        }
    }
    {
        const int kk = tn >> 2;           // component index of this quartet
        const int cbase = (tn & 3) * 4;   // x channel base within component
        const ull neg1 = pack2(-1.f, -1.f);
#pragma unroll
        for (int pp = 0; pp < 4; pp++) {
            const int pix = tm * 8 + 2 * pp;
            // sigma-stage matvec partials over this thread's 4 mu_new outputs
#pragma unroll
            for (int j = 0; j < 8; j++) {
                ull sp = pack2(0.f, 0.f);
#pragma unroll
                for (int o = 0; o < 4; o++) {
                    float w = sh[SH_S + (16 + tn * 4 + o) * 8 + j];
                    sp = ffma2(acc[o * 4 + pp], pack2(w, w), sp);
                }
                float2 f = unpack2(sp);
                atomicAdd(&sh[SH_SIG + j * 128 + pix], f.x);
                atomicAdd(&sh[SH_SIG + j * 128 + pix + 1], f.y);
            }
            // dist2 partials: (x - mu_new)^2 over this thread's 4 channels
            ull dacc = pack2(0.f, 0.f);
#pragma unroll
            for (int o = 0; o < 4; o++) {
                ull xv = *(const ull*)(sh + SH_A + (cbase + o) * 128 + pix);
                ull diff = ffma2(acc[o * 4 + pp], neg1, xv);
                dacc = ffma2(diff, diff, dacc);
            }
            float2 f = unpack2(dacc);
            atomicAdd(&sh[SH_D2 + kk * 128 + pix], f.x);
            atomicAdd(&sh[SH_D2 + kk * 128 + pix + 1], f.y);
        }
    }
    __syncthreads();

    // ---------------- stage 6: finalize sigma_new, dens2, gamma ------------
    if (tid < 128) {
        const int p = tid;
        float g = sh[SH_MISC + 24];  // bg
#pragma unroll
        for (int j = 0; j < 8; j++) {
            float s = sh[SH_MISC + 8 + j] + sh[SH_SIG + j * 128 + p];
#pragma unroll
            for (int c = 0; c < 16; c++)
                s = fmaf(sh[SH_S + c * 8 + j], sh[SH_A + c * 128 + p], s);
#pragma unroll
            for (int r = 0; r < 8; r++)
                s = fmaf(sh[SH_S + (144 + r) * 8 + j],
                         sh[SH_A + (144 + r) * 128 + p], s);
            float sn = __expf(fmaxf(s, 0.f));
            out[OFF_SIG + (b * 8 + j) * HW + hw0 + p] = sn;
            float s2 = sn * sn;
            float t = 6.283185307179586f * s2;
            float t2 = t * t, t4 = t2 * t2;
            float dens2 =
                __expf(-sh[SH_D2 + j * 128 + p] / (2.f * s2)) / (t4 * t4);
            g = fmaf(sh[SH_MISC + 16 + j], sh[SH_PIN + j * 128 + p] * dens2, g);
        }
        out[OFF_G + b * HW + hw0 + p] = 1.0f / (1.0f + __expf(-g));
    }
}

extern "C" void kernel_launch(void* const* d_in, const int* in_sizes, int n_in,
                              void* d_out, int out_size) {
    (void)in_sizes;
    (void)n_in;
    (void)out_size;
    const float* x = (const float*)d_in[0];
    const float* pi = (const float*)d_in[1];
    const float* mu = (const float*)d_in[2];
    const float* sigma = (const float*)d_in[3];
    const float* Wpi = (const float*)d_in[4];
    const float* bpi = (const float*)d_in[5];
    const float* Wmu = (const float*)d_in[6];
    const float* bmu = (const float*)d_in[7];
    const float* Wsig = (const float*)d_in[8];
    const float* bsig = (const float*)d_in[9];
    const float* Wg = (const float*)d_in[10];
    const float* bg = (const float*)d_in[11];
    float* out = (float*)d_out;

    cudaFuncSetAttribute(gmm_block_kernel,
                         cudaFuncAttributeMaxDynamicSharedMemorySize,
                         SMEM_BYTES);
    gmm_block_kernel<<<2048, 512, SMEM_BYTES>>>(x, pi, mu, sigma, Wpi, bpi, Wmu,
                                                bmu, Wsig, bsig, Wg, bg, out);
}

// round 6
// speedup vs baseline: 3.0559x; 3.0559x over previous
#include <cuda_runtime.h>

#define HW 16384
#define OFF_PI 0
#define OFF_MU 2097152
#define OFF_SIG 35651584
#define OFF_G 37748736

// shared layout (float offsets)
#define SH_W 0        // 152*128 : Wmu^T [c][o]
#define SH_S 19456    // 152*8   : Wsig^T [c][j]
#define SH_X 20672    // 16*128  : x tile [c][pix]
#define SH_R 22720    // 8*128   : rho   [k][pix]
#define SH_AL 23744   // 8*128   : alpha [k][pix]
#define SH_PIV 24768  // 8*128   : pi    [k][pix]
#define SH_SIG 25792  // 8*128   : sigma matvec mu_new partials [j][pix]
#define SH_D2 26816   // 8*128   : dist2 [k][pix]
#define SH_BMU 27840  // 128
#define SH_WPI 27968  // 128
#define SH_MISC 28096 // 32 : bpi[0..7] bsig[8..15] Wg[16..23] bg[24]
#define SH_TOT 28128
#define SMEM_BYTES (SH_TOT * 4)

typedef unsigned long long ull;

__device__ __forceinline__ ull pack2(float a, float b) {
    ull r;
    asm("mov.b64 %0, {%1,%2};" : "=l"(r) : "f"(a), "f"(b));
    return r;
}
__device__ __forceinline__ ull ffma2(ull a, ull b, ull c) {
    ull d;
    asm("fma.rn.f32x2 %0, %1, %2, %3;" : "=l"(d) : "l"(a), "l"(b), "l"(c));
    return d;
}
__device__ __forceinline__ float2 unpack2(ull v) {
    float2 f;
    asm("mov.b64 {%0,%1}, %2;" : "=f"(f.x), "=f"(f.y) : "l"(v));
    return f;
}

// one K-channel step: 8 broadcast LDS.128 (32 weights) + 64 ffma2
// acc[p][q]: pixel p (0..3), output pair q (0..15) of this warp's 32 outputs
__device__ __forceinline__ void gemm_step(ull acc[4][16], const float* wp,
                                          float4 v) {
    ulonglong2 W[8];
#pragma unroll
    for (int q = 0; q < 8; q++)
        W[q] = reinterpret_cast<const ulonglong2*>(wp)[q];
    ull vv[4] = {pack2(v.x, v.x), pack2(v.y, v.y), pack2(v.z, v.z),
                 pack2(v.w, v.w)};
#pragma unroll
    for (int q = 0; q < 8; q++) {
#pragma unroll
        for (int p = 0; p < 4; p++) {
            acc[p][2 * q] = ffma2(vv[p], W[q].x, acc[p][2 * q]);
            acc[p][2 * q + 1] = ffma2(vv[p], W[q].y, acc[p][2 * q + 1]);
        }
    }
}

extern "C" __global__ void __launch_bounds__(128, 2)
gmm_block_kernel(const float* __restrict__ x, const float* __restrict__ pi_in,
                 const float* __restrict__ mu, const float* __restrict__ sigma,
                 const float* __restrict__ Wpi, const float* __restrict__ bpi,
                 const float* __restrict__ Wmu, const float* __restrict__ bmu,
                 const float* __restrict__ Wsig, const float* __restrict__ bsig,
                 const float* __restrict__ Wg, const float* __restrict__ bg,
                 float* __restrict__ out) {
    extern __shared__ float sh[];
    const int tid = threadIdx.x;
    const int w = tid >> 5;      // warp = output quarter
    const int l = tid & 31;      // lane = pixel quad (pixels 4l..4l+3)
    const int blk = blockIdx.x;  // 2048 CTAs x 128 pixels
    const int b = blk >> 7;
    const int hw0 = (blk & 127) << 7;

    // ---------------- stage 1: stage weights + x tile ----------------------
    {
        const float* wrow = Wmu + tid * 152;  // thread owns output row tid
#pragma unroll 4
        for (int c = 0; c < 152; c++) sh[SH_W + c * 128 + tid] = wrow[c];
    }
    for (int i = tid; i < 1216; i += 128) {  // Wsig[j][c] -> shS[c][j]
        int c = i >> 3, j = i & 7;
        sh[SH_S + c * 8 + j] = Wsig[j * 152 + c];
    }
    for (int i = tid; i < 2048; i += 128) {
        int c = i >> 7, p = i & 127;
        sh[SH_X + i] = x[(b * 16 + c) * HW + hw0 + p];
    }
    sh[SH_BMU + tid] = bmu[tid];
    sh[SH_WPI + tid] = Wpi[tid];
    if (tid < 8) {
        sh[SH_MISC + tid] = bpi[tid];
        sh[SH_MISC + 8 + tid] = bsig[tid];
        sh[SH_MISC + 16 + tid] = Wg[tid];
    }
    if (tid == 0) sh[SH_MISC + 24] = bg[0];
    for (int i = tid; i < 1024; i += 128) sh[SH_SIG + i] = 0.f;
    __syncthreads();

    const int obase = w * 32;
    const float* mup = mu + (b * 128) * HW + hw0 + 4 * l;

    ull acc[4][16];
#pragma unroll
    for (int q = 0; q < 16; q++) {
        ull bb = *reinterpret_cast<const ull*>(sh + SH_BMU + obase + 2 * q);
#pragma unroll
        for (int p = 0; p < 4; p++) acc[p][q] = bb;
    }

    // ---------------- phase A: x channels 0..15 ----------------------------
#pragma unroll 4
    for (int c = 0; c < 16; c++) {
        float4 xv = *reinterpret_cast<const float4*>(sh + SH_X + c * 128 + 4 * l);
        gemm_step(acc, sh + SH_W + c * 128 + obase, xv);
    }

    // ---------------- phase B: mu channels, dist split across warps --------
#pragma unroll 1
    for (int k = 0; k < 8; k++) {
        const float* mk = mup + (k * 16) * HW;
        const float* wk = sh + SH_W + (16 + k * 16) * 128 + obase;
        if ((k >> 1) == w) {
            float4 dk = make_float4(0.f, 0.f, 0.f, 0.f);
#pragma unroll 4
            for (int c = 0; c < 16; c++) {
                float4 mv = *reinterpret_cast<const float4*>(mk + c * HW);
                float4 xv =
                    *reinterpret_cast<const float4*>(sh + SH_X + c * 128 + 4 * l);
                float d0 = xv.x - mv.x, d1 = xv.y - mv.y;
                float d2 = xv.z - mv.z, d3 = xv.w - mv.w;
                dk.x = fmaf(d0, d0, dk.x);
                dk.y = fmaf(d1, d1, dk.y);
                dk.z = fmaf(d2, d2, dk.z);
                dk.w = fmaf(d3, d3, dk.w);
                gemm_step(acc, wk + c * 128, mv);
            }
            float4 sg = *reinterpret_cast<const float4*>(
                sigma + (b * 8 + k) * HW + hw0 + 4 * l);
            float4 pv = *reinterpret_cast<const float4*>(
                pi_in + (b * 8 + k) * HW + hw0 + 4 * l);
            float4 al4, rho4;
            {
                float s2 = sg.x * sg.x;
                float t = 6.283185307179586f * s2;
                float t2 = t * t, t4 = t2 * t2;
                float dens = __expf(-dk.x / (2.f * s2)) / (t4 * t4);
                al4.x = pv.x * dens;
                rho4.x = al4.x * dens;
            }
            {
                float s2 = sg.y * sg.y;
                float t = 6.283185307179586f * s2;
                float t2 = t * t, t4 = t2 * t2;
                float dens = __expf(-dk.y / (2.f * s2)) / (t4 * t4);
                al4.y = pv.y * dens;
                rho4.y = al4.y * dens;
            }
            {
                float s2 = sg.z * sg.z;
                float t = 6.283185307179586f * s2;
                float t2 = t * t, t4 = t2 * t2;
                float dens = __expf(-dk.z / (2.f * s2)) / (t4 * t4);
                al4.z = pv.z * dens;
                rho4.z = al4.z * dens;
            }
            {
                float s2 = sg.w * sg.w;
                float t = 6.283185307179586f * s2;
                float t2 = t * t, t4 = t2 * t2;
                float dens = __expf(-dk.w / (2.f * s2)) / (t4 * t4);
                al4.w = pv.w * dens;
                rho4.w = al4.w * dens;
            }
            *reinterpret_cast<float4*>(sh + SH_AL + k * 128 + 4 * l) = al4;
            *reinterpret_cast<float4*>(sh + SH_PIV + k * 128 + 4 * l) = pv;
            *reinterpret_cast<float4*>(sh + SH_R + k * 128 + 4 * l) = rho4;
        } else {
#pragma unroll 4
            for (int c = 0; c < 16; c++) {
                float4 mv = *reinterpret_cast<const float4*>(mk + c * HW);
                gemm_step(acc, wk + c * 128, mv);
            }
        }
    }
    __syncthreads();

    // ---------------- phase C: rho channels 144..151 -----------------------
#pragma unroll 4
    for (int r = 0; r < 8; r++) {
        float4 rv = *reinterpret_cast<const float4*>(sh + SH_R + r * 128 + 4 * l);
        gemm_step(acc, sh + SH_W + (144 + r) * 128 + obase, rv);
    }

    // ---------------- epilogue: relu, store mu_new, d2, sigma partials -----
    float* outMu = out + OFF_MU + (b * 128 + obase) * HW + hw0 + 4 * l;
    float4 d2lo = make_float4(0.f, 0.f, 0.f, 0.f);
    float4 d2hi = make_float4(0.f, 0.f, 0.f, 0.f);
    ull sp[4][4];
#pragma unroll
    for (int p = 0; p < 4; p++)
#pragma unroll
        for (int t = 0; t < 4; t++) sp[p][t] = pack2(0.f, 0.f);

#pragma unroll
    for (int q = 0; q < 16; q++) {
        float2 f[4];
#pragma unroll
        for (int p = 0; p < 4; p++) {
            f[p] = unpack2(acc[p][q]);
            f[p].x = fmaxf(f[p].x, 0.f);
            f[p].y = fmaxf(f[p].y, 0.f);
        }
        *reinterpret_cast<float4*>(outMu + (2 * q) * HW) =
            make_float4(f[0].x, f[1].x, f[2].x, f[3].x);
        *reinterpret_cast<float4*>(outMu + (2 * q + 1) * HW) =
            make_float4(f[0].y, f[1].y, f[2].y, f[3].y);

        const int xc = (2 * q) & 15;
        float4 xa = *reinterpret_cast<const float4*>(sh + SH_X + xc * 128 + 4 * l);
        float4 xb =
            *reinterpret_cast<const float4*>(sh + SH_X + (xc + 1) * 128 + 4 * l);
        float da0 = xa.x - f[0].x, db0 = xb.x - f[0].y;
        float da1 = xa.y - f[1].x, db1 = xb.y - f[1].y;
        float da2 = xa.z - f[2].x, db2 = xb.z - f[2].y;
        float da3 = xa.w - f[3].x, db3 = xb.w - f[3].y;
        if (q < 8) {
            d2lo.x = fmaf(da0, da0, fmaf(db0, db0, d2lo.x));
            d2lo.y = fmaf(da1, da1, fmaf(db1, db1, d2lo.y));
            d2lo.z = fmaf(da2, da2, fmaf(db2, db2, d2lo.z));
            d2lo.w = fmaf(da3, da3, fmaf(db3, db3, d2lo.w));
        } else {
            d2hi.x = fmaf(da0, da0, fmaf(db0, db0, d2hi.x));
            d2hi.y = fmaf(da1, da1, fmaf(db1, db1, d2hi.y));
            d2hi.z = fmaf(da2, da2, fmaf(db2, db2, d2hi.z));
            d2hi.w = fmaf(da3, da3, fmaf(db3, db3, d2hi.w));
        }
        const ulonglong2* wsa = reinterpret_cast<const ulonglong2*>(
            sh + SH_S + (16 + obase + 2 * q) * 8);
        ulonglong2 wa0 = wsa[0], wa1 = wsa[1];
        ulonglong2 wb0 = wsa[2], wb1 = wsa[3];  // next channel row (contiguous)
#pragma unroll
        for (int p = 0; p < 4; p++) {
            ull mx = pack2(f[p].x, f[p].x);
            ull my = pack2(f[p].y, f[p].y);
            sp[p][0] = ffma2(mx, wa0.x, sp[p][0]);
            sp[p][1] = ffma2(mx, wa0.y, sp[p][1]);
            sp[p][2] = ffma2(mx, wa1.x, sp[p][2]);
            sp[p][3] = ffma2(mx, wa1.y, sp[p][3]);
            sp[p][0] = ffma2(my, wb0.x, sp[p][0]);
            sp[p][1] = ffma2(my, wb0.y, sp[p][1]);
            sp[p][2] = ffma2(my, wb1.x, sp[p][2]);
            sp[p][3] = ffma2(my, wb1.y, sp[p][3]);
        }
    }
    *reinterpret_cast<float4*>(sh + SH_D2 + (2 * w) * 128 + 4 * l) = d2lo;
    *reinterpret_cast<float4*>(sh + SH_D2 + (2 * w + 1) * 128 + 4 * l) = d2hi;
#pragma unroll
    for (int p = 0; p < 4; p++) {
#pragma unroll
        for (int t = 0; t < 4; t++) {
            float2 fz = unpack2(sp[p][t]);
            atomicAdd(&sh[SH_SIG + (2 * t) * 128 + 4 * l + p], fz.x);
            atomicAdd(&sh[SH_SIG + (2 * t + 1) * 128 + 4 * l + p], fz.y);
        }
    }
    __syncthreads();

    // ---------------- stage 6: per-pixel finalize --------------------------
    {
        const int p = tid;
        float piv[8], al[8], z[8], pin[8];
#pragma unroll
        for (int k = 0; k < 8; k++) {
            piv[k] = sh[SH_PIV + k * 128 + p];
            al[k] = sh[SH_AL + k * 128 + p];
        }
        float zmax = -1e30f;
#pragma unroll
        for (int j = 0; j < 8; j++) {
            float zj = sh[SH_MISC + j];
#pragma unroll
            for (int i = 0; i < 8; i++) {
                zj = fmaf(sh[SH_WPI + j * 16 + i], piv[i], zj);
                zj = fmaf(sh[SH_WPI + j * 16 + 8 + i], al[i], zj);
            }
            z[j] = zj;
            zmax = fmaxf(zmax, zj);
        }
        float s = 0.f;
#pragma unroll
        for (int j = 0; j < 8; j++) {
            z[j] = __expf(z[j] - zmax);
            s += z[j];
        }
        float inv = 1.0f / s;
#pragma unroll
        for (int j = 0; j < 8; j++) {
            pin[j] = z[j] * inv;
            out[OFF_PI + (b * 8 + j) * HW + hw0 + p] = pin[j];
        }
        float g = sh[SH_MISC + 24];
#pragma unroll
        for (int j = 0; j < 8; j++) {
            float sv = sh[SH_MISC + 8 + j] + sh[SH_SIG + j * 128 + p];
#pragma unroll
            for (int c = 0; c < 16; c++)
                sv = fmaf(sh[SH_S + c * 8 + j], sh[SH_X + c * 128 + p], sv);
#pragma unroll
            for (int r = 0; r < 8; r++)
                sv = fmaf(sh[SH_S + (144 + r) * 8 + j], sh[SH_R + r * 128 + p],
                          sv);
            float sn = __expf(fmaxf(sv, 0.f));
            out[OFF_SIG + (b * 8 + j) * HW + hw0 + p] = sn;
            float s2 = sn * sn;
            float t = 6.283185307179586f * s2;
            float t2 = t * t, t4 = t2 * t2;
            float dens2 =
                __expf(-sh[SH_D2 + j * 128 + p] / (2.f * s2)) / (t4 * t4);
            g = fmaf(sh[SH_MISC + 16 + j], pin[j] * dens2, g);
        }
        out[OFF_G + b * HW + hw0 + p] = 1.0f / (1.0f + __expf(-g));
    }
}

extern "C" void kernel_launch(void* const* d_in, const int* in_sizes, int n_in,
                              void* d_out, int out_size) {
    (void)in_sizes;
    (void)n_in;
    (void)out_size;
    const float* x = (const float*)d_in[0];
    const float* pi = (const float*)d_in[1];
    const float* mu = (const float*)d_in[2];
    const float* sigma = (const float*)d_in[3];
    const float* Wpi = (const float*)d_in[4];
    const float* bpi = (const float*)d_in[5];
    const float* Wmu = (const float*)d_in[6];
    const float* bmu = (const float*)d_in[7];
    const float* Wsig = (const float*)d_in[8];
    const float* bsig = (const float*)d_in[9];
    const float* Wg = (const float*)d_in[10];
    const float* bg = (const float*)d_in[11];
    float* out = (float*)d_out;

    cudaFuncSetAttribute(gmm_block_kernel,
                         cudaFuncAttributeMaxDynamicSharedMemorySize,
                         SMEM_BYTES);
    gmm_block_kernel<<<2048, 128, SMEM_BYTES>>>(x, pi, mu, sigma, Wpi, bpi, Wmu,
                                                bmu, Wsig, bsig, Wg, bg, out);
}

// round 7
// speedup vs baseline: 3.1035x; 1.0156x over previous
#include <cuda_runtime.h>

#define HW 16384
#define OFF_PI 0
#define OFF_MU 2097152
#define OFF_SIG 35651584
#define OFF_G 37748736

// shared layout (float offsets). SH_W is reused as the mu_new tile (SH_MN)
// after the GEMM completes (weights dead by then).
#define SH_W 0         // 152*128 = 19456 : Wmu^T [c][o]  /  mu_new [o][pix]
#define SH_S 19456     // 152*8   : Wsig^T [c][j]
#define SH_X 20672     // 16*128  : x tile [c][pix]
#define SH_R 22720     // 8*128   : rho   [k][pix]
#define SH_AL 23744    // 8*128   : alpha [k][pix]
#define SH_PIV 24768   // 8*128   : pi    [k][pix]
#define SH_BMU 25792   // 128
#define SH_WPI 25920   // 128
#define SH_MISC 26048  // 32 : bpi[0..7] bsig[8..15] Wg[16..23] bg[24]
#define SH_TOT 26080
#define SMEM_BYTES (SH_TOT * 4)

typedef unsigned long long ull;

__device__ __forceinline__ ull pack2(float a, float b) {
    ull r;
    asm("mov.b64 %0, {%1,%2};" : "=l"(r) : "f"(a), "f"(b));
    return r;
}
__device__ __forceinline__ ull ffma2(ull a, ull b, ull c) {
    ull d;
    asm("fma.rn.f32x2 %0, %1, %2, %3;" : "=l"(d) : "l"(a), "l"(b), "l"(c));
    return d;
}
__device__ __forceinline__ float2 unpack2(ull v) {
    float2 f;
    asm("mov.b64 {%0,%1}, %2;" : "=f"(f.x), "=f"(f.y) : "l"(v));
    return f;
}

// one K-channel step for 16 outputs x 4 pixels:
// 4 broadcast LDS.128 (16 weights) + 32 ffma2
__device__ __forceinline__ void gemm_step16(ull acc[4][8], const float* wp,
                                            float4 v) {
    ulonglong2 W0 = reinterpret_cast<const ulonglong2*>(wp)[0];
    ulonglong2 W1 = reinterpret_cast<const ulonglong2*>(wp)[1];
    ulonglong2 W2 = reinterpret_cast<const ulonglong2*>(wp)[2];
    ulonglong2 W3 = reinterpret_cast<const ulonglong2*>(wp)[3];
    ull wv[8] = {W0.x, W0.y, W1.x, W1.y, W2.x, W2.y, W3.x, W3.y};
    ull vv[4] = {pack2(v.x, v.x), pack2(v.y, v.y), pack2(v.z, v.z),
                 pack2(v.w, v.w)};
#pragma unroll
    for (int q = 0; q < 8; q++) {
#pragma unroll
        for (int p = 0; p < 4; p++)
            acc[p][q] = ffma2(vv[p], wv[q], acc[p][q]);
    }
}

extern "C" __global__ void __launch_bounds__(256, 2)
gmm_block_kernel(const float* __restrict__ x, const float* __restrict__ pi_in,
                 const float* __restrict__ mu, const float* __restrict__ sigma,
                 const float* __restrict__ Wpi, const float* __restrict__ bpi,
                 const float* __restrict__ Wmu, const float* __restrict__ bmu,
                 const float* __restrict__ Wsig, const float* __restrict__ bsig,
                 const float* __restrict__ Wg, const float* __restrict__ bg,
                 float* __restrict__ out) {
    extern __shared__ float sh[];
    const int tid = threadIdx.x;
    const int w = tid >> 5;      // warp = component (16 outputs), 0..7
    const int l = tid & 31;      // lane = pixel quad (pixels 4l..4l+3)
    const int blk = blockIdx.x;  // 2048 CTAs x 128 pixels
    const int b = blk >> 7;
    const int hw0 = (blk & 127) << 7;

    // ---------------- stage 1: stage weights + x tile ----------------------
    for (int i = tid; i < 19456; i += 256) {  // Wmu[o][c] -> shW[c][o]
        int o = i / 152, c = i - o * 152;
        sh[SH_W + c * 128 + o] = Wmu[i];
    }
    for (int i = tid; i < 1216; i += 256) {  // Wsig[j][c] -> shS[c][j]
        int j = i / 152, c = i - j * 152;
        sh[SH_S + c * 8 + j] = Wsig[i];
    }
    for (int i = tid; i < 2048; i += 256) {
        int c = i >> 7, p = i & 127;
        sh[SH_X + i] = x[(b * 16 + c) * HW + hw0 + p];
    }
    if (tid < 128) {
        sh[SH_BMU + tid] = bmu[tid];
        sh[SH_WPI + tid] = Wpi[tid];
    } else if (tid < 136) {
        int k = tid - 128;
        sh[SH_MISC + k] = bpi[k];
        sh[SH_MISC + 8 + k] = bsig[k];
        sh[SH_MISC + 16 + k] = Wg[k];
    }
    if (tid == 255) sh[SH_MISC + 24] = bg[0];
    __syncthreads();

    const int obase = w * 16;
    const float* mup = mu + (b * 128) * HW + hw0 + 4 * l;

    ull acc[4][8];
#pragma unroll
    for (int q = 0; q < 8; q++) {
        ull bb = *reinterpret_cast<const ull*>(sh + SH_BMU + obase + 2 * q);
#pragma unroll
        for (int p = 0; p < 4; p++) acc[p][q] = bb;
    }

    // ---------------- phase A: x channels 0..15 ----------------------------
#pragma unroll 4
    for (int c = 0; c < 16; c++) {
        float4 xv =
            *reinterpret_cast<const float4*>(sh + SH_X + c * 128 + 4 * l);
        gemm_step16(acc, sh + SH_W + c * 128 + obase, xv);
    }

    // ---------------- phase B: mu channels; warp w fuses dist for k==w -----
#pragma unroll 1
    for (int k = 0; k < 8; k++) {
        const float* mk = mup + (k * 16) * HW;
        const float* wk = sh + SH_W + (16 + k * 16) * 128 + obase;
        if (k == w) {
            float4 dk = make_float4(0.f, 0.f, 0.f, 0.f);
#pragma unroll 4
            for (int c = 0; c < 16; c++) {
                float4 mv = *reinterpret_cast<const float4*>(mk + c * HW);
                float4 xv = *reinterpret_cast<const float4*>(sh + SH_X +
                                                             c * 128 + 4 * l);
                float d0 = xv.x - mv.x, d1 = xv.y - mv.y;
                float d2 = xv.z - mv.z, d3 = xv.w - mv.w;
                dk.x = fmaf(d0, d0, dk.x);
                dk.y = fmaf(d1, d1, dk.y);
                dk.z = fmaf(d2, d2, dk.z);
                dk.w = fmaf(d3, d3, dk.w);
                gemm_step16(acc, wk + c * 128, mv);
            }
            float4 sg = *reinterpret_cast<const float4*>(
                sigma + (b * 8 + k) * HW + hw0 + 4 * l);
            float4 pv = *reinterpret_cast<const float4*>(
                pi_in + (b * 8 + k) * HW + hw0 + 4 * l);
            float4 al4, rho4;
            {
                float s2 = sg.x * sg.x;
                float t = 6.283185307179586f * s2;
                float t2 = t * t, t4 = t2 * t2;
                float dens = __expf(-dk.x / (2.f * s2)) / (t4 * t4);
                al4.x = pv.x * dens;
                rho4.x = al4.x * dens;
            }
            {
                float s2 = sg.y * sg.y;
                float t = 6.283185307179586f * s2;
                float t2 = t * t, t4 = t2 * t2;
                float dens = __expf(-dk.y / (2.f * s2)) / (t4 * t4);
                al4.y = pv.y * dens;
                rho4.y = al4.y * dens;
            }
            {
                float s2 = sg.z * sg.z;
                float t = 6.283185307179586f * s2;
                float t2 = t * t, t4 = t2 * t2;
                float dens = __expf(-dk.z / (2.f * s2)) / (t4 * t4);
                al4.z = pv.z * dens;
                rho4.z = al4.z * dens;
            }
            {
                float s2 = sg.w * sg.w;
                float t = 6.283185307179586f * s2;
                float t2 = t * t, t4 = t2 * t2;
                float dens = __expf(-dk.w / (2.f * s2)) / (t4 * t4);
                al4.w = pv.w * dens;
                rho4.w = al4.w * dens;
            }
            *reinterpret_cast<float4*>(sh + SH_AL + k * 128 + 4 * l) = al4;
            *reinterpret_cast<float4*>(sh + SH_PIV + k * 128 + 4 * l) = pv;
            *reinterpret_cast<float4*>(sh + SH_R + k * 128 + 4 * l) = rho4;
        } else {
#pragma unroll 4
            for (int c = 0; c < 16; c++) {
                float4 mv = *reinterpret_cast<const float4*>(mk + c * HW);
                gemm_step16(acc, wk + c * 128, mv);
            }
        }
    }
    __syncthreads();

    // ---------------- phase C: rho channels 144..151 -----------------------
#pragma unroll 4
    for (int r = 0; r < 8; r++) {
        float4 rv =
            *reinterpret_cast<const float4*>(sh + SH_R + r * 128 + 4 * l);
        gemm_step16(acc, sh + SH_W + (144 + r) * 128 + obase, rv);
    }
    __syncthreads();  // all weight reads done; SH_W becomes the mu_new tile

    // ---------------- epilogue: relu, store mu_new (gmem + smem tile) ------
    {
        float* outMu =
            out + OFF_MU + (b * 128 + obase) * HW + hw0 + 4 * l;
#pragma unroll
        for (int q = 0; q < 8; q++) {
            float2 f0 = unpack2(acc[0][q]);
            float2 f1 = unpack2(acc[1][q]);
            float2 f2 = unpack2(acc[2][q]);
            float2 f3 = unpack2(acc[3][q]);
            float4 lo = make_float4(fmaxf(f0.x, 0.f), fmaxf(f1.x, 0.f),
                                    fmaxf(f2.x, 0.f), fmaxf(f3.x, 0.f));
            float4 hi = make_float4(fmaxf(f0.y, 0.f), fmaxf(f1.y, 0.f),
                                    fmaxf(f2.y, 0.f), fmaxf(f3.y, 0.f));
            *reinterpret_cast<float4*>(outMu + (2 * q) * HW) = lo;
            *reinterpret_cast<float4*>(outMu + (2 * q + 1) * HW) = hi;
            *reinterpret_cast<float4*>(sh + SH_W + (obase + 2 * q) * 128 +
                                       4 * l) = lo;
            *reinterpret_cast<float4*>(sh + SH_W + (obase + 2 * q + 1) * 128 +
                                       4 * l) = hi;
        }
    }
    __syncthreads();

    // ---------------- finalize (128 threads, one pixel each) ---------------
    if (tid < 128) {
        const int p = tid;
        // softmax over Wpi @ [pi, alpha] + bpi
        float piv[8], al[8], z[8], pin[8];
#pragma unroll
        for (int k = 0; k < 8; k++) {
            piv[k] = sh[SH_PIV + k * 128 + p];
            al[k] = sh[SH_AL + k * 128 + p];
        }
        float zmax = -1e30f;
#pragma unroll
        for (int j = 0; j < 8; j++) {
            float zj = sh[SH_MISC + j];
#pragma unroll
            for (int i = 0; i < 8; i++) {
                zj = fmaf(sh[SH_WPI + j * 16 + i], piv[i], zj);
                zj = fmaf(sh[SH_WPI + j * 16 + 8 + i], al[i], zj);
            }
            z[j] = zj;
            zmax = fmaxf(zmax, zj);
        }
        float s = 0.f;
#pragma unroll
        for (int j = 0; j < 8; j++) {
            z[j] = __expf(z[j] - zmax);
            s += z[j];
        }
        float inv = 1.0f / s;
#pragma unroll
        for (int j = 0; j < 8; j++) {
            pin[j] = z[j] * inv;
            out[OFF_PI + (b * 8 + j) * HW + hw0 + p] = pin[j];
        }

        // sigma matvec over all 152 channels + fused dist2 on mu_new
        float sj[8];
#pragma unroll
        for (int j = 0; j < 8; j++) sj[j] = sh[SH_MISC + 8 + j];
#pragma unroll 4
        for (int c = 0; c < 16; c++) {
            float xv = sh[SH_X + c * 128 + p];
#pragma unroll
            for (int j = 0; j < 8; j++)
                sj[j] = fmaf(sh[SH_S + c * 8 + j], xv, sj[j]);
        }
        float d2[8];
#pragma unroll 1
        for (int k = 0; k < 8; k++) {
            float dk = 0.f;
#pragma unroll
            for (int c2 = 0; c2 < 16; c2++) {
                int c = k * 16 + c2;
                float mn = sh[SH_W + c * 128 + p];  // mu_new tile
#pragma unroll
                for (int j = 0; j < 8; j++)
                    sj[j] = fmaf(sh[SH_S + (16 + c) * 8 + j], mn, sj[j]);
                float d = sh[SH_X + c2 * 128 + p] - mn;
                dk = fmaf(d, d, dk);
            }
            d2[k] = dk;
        }
#pragma unroll
        for (int r = 0; r < 8; r++) {
            float rv = sh[SH_R + r * 128 + p];
#pragma unroll
            for (int j = 0; j < 8; j++)
                sj[j] = fmaf(sh[SH_S + (144 + r) * 8 + j], rv, sj[j]);
        }

        float g = sh[SH_MISC + 24];
#pragma unroll
        for (int j = 0; j < 8; j++) {
            float sn = __expf(fmaxf(sj[j], 0.f));
            out[OFF_SIG + (b * 8 + j) * HW + hw0 + p] = sn;
            float s2 = sn * sn;
            float t = 6.283185307179586f * s2;
            float t2 = t * t, t4 = t2 * t2;
            float dens2 = __expf(-d2[j] / (2.f * s2)) / (t4 * t4);
            g = fmaf(sh[SH_MISC + 16 + j], pin[j] * dens2, g);
        }
        out[OFF_G + b * HW + hw0 + p] = 1.0f / (1.0f + __expf(-g));
    }
}

extern "C" void kernel_launch(void* const* d_in, const int* in_sizes, int n_in,
                              void* d_out, int out_size) {
    (void)in_sizes;
    (void)n_in;
    (void)out_size;
    const float* x = (const float*)d_in[0];
    const float* pi = (const float*)d_in[1];
    const float* mu = (const float*)d_in[2];
    const float* sigma = (const float*)d_in[3];
    const float* Wpi = (const float*)d_in[4];
    const float* bpi = (const float*)d_in[5];
    const float* Wmu = (const float*)d_in[6];
    const float* bmu = (const float*)d_in[7];
    const float* Wsig = (const float*)d_in[8];
    const float* bsig = (const float*)d_in[9];
    const float* Wg = (const float*)d_in[10];
    const float* bg = (const float*)d_in[11];
    float* out = (float*)d_out;

    cudaFuncSetAttribute(gmm_block_kernel,
                         cudaFuncAttributeMaxDynamicSharedMemorySize,
                         SMEM_BYTES);
    gmm_block_kernel<<<2048, 256, SMEM_BYTES>>>(x, pi, mu, sigma, Wpi, bpi, Wmu,
                                                bmu, Wsig, bsig, Wg, bg, out);
}